// round 15
// baseline (speedup 1.0000x reference)
#include <cuda_runtime.h>
#include <cstdint>

#define LOG2E 1.4426950408889634f

// ---------------- scratch ----------------
__device__ float g_Wh[8 * 1024 * 256];   // [b][n][h*32+d]
__device__ float g_e1[64 * 1024];
__device__ float g_e2[64 * 1024];
__device__ float g_maxe2[64];
__device__ float g_Bhi[64 * 128 * 256];  // [bh][chunk][d*8 + pos], pos pairs (j, j+4)
__device__ float g_Blo[64 * 128 * 256];

// ---------------- helpers ----------------
__device__ __forceinline__ void fma2(unsigned long long& d, unsigned long long a,
                                     unsigned long long b) {
    asm("fma.rn.f32x2 %0, %1, %2, %0;" : "+l"(d) : "l"(a), "l"(b));
}
__device__ __forceinline__ unsigned long long dup2(float v) {
    unsigned long long r;
    asm("mov.b64 %0, {%1,%1};" : "=l"(r) : "f"(v));
    return r;
}
__device__ __forceinline__ void upk2(unsigned long long v, float& lo, float& hi) {
    asm("mov.b64 {%0,%1}, %2;" : "=f"(lo), "=f"(hi) : "l"(v));
}
__device__ __forceinline__ float ex2(float x) {
    float r;
    asm("ex2.approx.ftz.f32 %0, %1;" : "=f"(r) : "f"(x));
    return r;
}
__device__ __forceinline__ float tf32_hi(float x) {
    uint32_t u;
    asm("cvt.rna.tf32.f32 %0, %1;" : "=r"(u) : "f"(x));
    return __uint_as_float(u);
}
// m16n8k8 tf32 MMA, fp32 accumulate (legacy HMMA path, plain sm_80+ PTX)
__device__ __forceinline__ void mma8(float* c, uint32_t a0, uint32_t a1,
                                     uint32_t a2, uint32_t a3,
                                     uint32_t b0, uint32_t b1) {
    asm volatile(
        "mma.sync.aligned.m16n8k8.row.col.f32.tf32.tf32.f32 "
        "{%0,%1,%2,%3},{%4,%5,%6,%7},{%8,%9},{%0,%1,%2,%3};"
        : "+f"(c[0]), "+f"(c[1]), "+f"(c[2]), "+f"(c[3])
        : "r"(a0), "r"(a1), "r"(a2), "r"(a3), "r"(b0), "r"(b1));
}

// ---------------- kernel 1: Wh = nf(8192x256) @ Wcat(256x256) ----------------
__global__ void __launch_bounds__(256)
gemm_wh_kernel(const float* __restrict__ A, const float* __restrict__ Wm) {
    __shared__ __align__(16) float as[16][132];
    __shared__ __align__(16) float bs[16][64];

    const int row0 = blockIdx.x * 128;
    const int col0 = blockIdx.y * 64;
    const int t = threadIdx.x;
    const int tx = t & 15, ty = t >> 4;

    unsigned long long acc[8][2];
#pragma unroll
    for (int r = 0; r < 8; r++) { acc[r][0] = 0ull; acc[r][1] = 0ull; }

    float4 a_reg[2], b_reg;
    auto load_tile = [&](int k0) {
#pragma unroll
        for (int l = 0; l < 2; l++) {
            int e = t + l * 256;
            int r = e >> 2, kq = e & 3;
            a_reg[l] = *(const float4*)&A[(size_t)(row0 + r) * 256 + k0 + kq * 4];
        }
        {
            int kk = t >> 4, cq = t & 15;
            int c = col0 + cq * 4;
            b_reg = *(const float4*)&Wm[(size_t)(c >> 5) * 8192 +
                                        (size_t)(k0 + kk) * 32 + (c & 31)];
        }
    };

    load_tile(0);
    for (int k0 = 0; k0 < 256; k0 += 16) {
#pragma unroll
        for (int l = 0; l < 2; l++) {
            int e = t + l * 256;
            int r = e >> 2, kq = e & 3;
            as[kq * 4 + 0][r] = a_reg[l].x;
            as[kq * 4 + 1][r] = a_reg[l].y;
            as[kq * 4 + 2][r] = a_reg[l].z;
            as[kq * 4 + 3][r] = a_reg[l].w;
        }
        {
            int kk = t >> 4, cq = t & 15;
            *(float4*)&bs[kk][cq * 4] = b_reg;
        }
        __syncthreads();
        if (k0 + 16 < 256) load_tile(k0 + 16);
#pragma unroll
        for (int kk = 0; kk < 16; kk++) {
            float4 a0 = *(const float4*)&as[kk][ty * 4];
            float4 a1 = *(const float4*)&as[kk][ty * 4 + 64];
            ulonglong2 b0 = *(const ulonglong2*)&bs[kk][tx * 4];
            unsigned long long ad[8];
            ad[0] = dup2(a0.x); ad[1] = dup2(a0.y); ad[2] = dup2(a0.z); ad[3] = dup2(a0.w);
            ad[4] = dup2(a1.x); ad[5] = dup2(a1.y); ad[6] = dup2(a1.z); ad[7] = dup2(a1.w);
#pragma unroll
            for (int r = 0; r < 8; r++) {
                fma2(acc[r][0], b0.x, ad[r]);
                fma2(acc[r][1], b0.y, ad[r]);
            }
        }
        __syncthreads();
    }
#pragma unroll
    for (int r = 0; r < 8; r++) {
        int gr = row0 + ((r < 4) ? (ty * 4 + r) : (64 + ty * 4 + r - 4));
        float4 o;
        upk2(acc[r][0], o.x, o.y);
        upk2(acc[r][1], o.z, o.w);
        *(float4*)&g_Wh[(size_t)gr * 256 + col0 + tx * 4] = o;
    }
}

// ---------------- kernel 2: e1, e2, max(e2) per (b,h) ----------------
__global__ void compute_e_kernel(const float* __restrict__ a) {
    const int bh = blockIdx.x;
    const int b = bh >> 3, h = bh & 7;
    const int tid = threadIdx.x;
    const int warp = tid >> 5, lane = tid & 31;

    const float a1v = a[h * 64 + lane];
    const float a2v = a[h * 64 + 32 + lane];
    __shared__ float wmax[8];

    const float* base = g_Wh + (size_t)(b * 1024) * 256 + h * 32;
    float mx = -1e30f;
    for (int nn = 0; nn < 128; nn++) {
        int n = warp * 128 + nn;
        float wh = base[(size_t)n * 256 + lane];
        float x = wh * a1v;
        float y = wh * a2v;
#pragma unroll
        for (int s = 16; s >= 1; s >>= 1) {
            x += __shfl_xor_sync(0xffffffffu, x, s);
            y += __shfl_xor_sync(0xffffffffu, y, s);
        }
        if (lane == 0) {
            g_e1[bh * 1024 + n] = x;
            g_e2[bh * 1024 + n] = y;
        }
        mx = fmaxf(mx, y);
    }
    if (lane == 0) wmax[warp] = mx;
    __syncthreads();
    if (tid == 0) {
        float m = wmax[0];
#pragma unroll
        for (int w = 1; w < 8; w++) m = fmaxf(m, wmax[w]);
        g_maxe2[bh] = m;
    }
}

// ---------------- kernel 2b: B-operand prep (WhT pair-interleaved hi/lo) ----------------
// g_B*[bh][ch][d*8 + pos], pos order per 8-j chunk: [j0 j4 j1 j5 j2 j6 j3 j7]
__global__ void __launch_bounds__(256)
prep_b_kernel() {
    const int bh = blockIdx.x;
    const int b = bh >> 3, h = bh & 7;
    const int tid = threadIdx.x;
    for (int k = 0; k < 128; k++) {
        int idx = tid + k * 256;
        int ch = idx >> 8, rem = idx & 255;
        int d = rem >> 3, pos = rem & 7;
        int jp = (pos >> 1) + ((pos & 1) << 2);
        float v = g_Wh[(size_t)(b * 1024 + ch * 8 + jp) * 256 + h * 32 + d];
        float hi = tf32_hi(v);
        g_Bhi[(size_t)bh * 32768 + idx] = hi;
        g_Blo[(size_t)bh * 32768 + idx] = v - hi;
    }
}

// ---------------- kernel 3: fused attention via mma.sync tf32 3-split ----------------
// CTA = (b,h) x half (512 rows); warp owns 32 rows, fully warp-autonomous.
// smem floats: e2[1024] | sums[512] | per-warp P tiles hi/lo 32x36 each
#define ROWF 36
#define PW (2 * 32 * ROWF)
#define SM_SUMS 1024
#define SM_P 1536
#define ATTN_SMEM ((SM_P + 16 * PW) * 4)

__global__ void __launch_bounds__(512, 1)
gat_attn_mma(const int* __restrict__ adj, const float* __restrict__ bias,
             float* __restrict__ out) {
    extern __shared__ __align__(16) float sm[];
    float* e2s = sm;
    float* sums_s = sm + SM_SUMS;

    const int bh = blockIdx.x >> 1, hv = blockIdx.x & 1;
    const int b = bh >> 3, h = bh & 7;
    const int tid = threadIdx.x, w = tid >> 5, lane = tid & 31;

    for (int n = tid; n < 1024; n += 512) e2s[n] = g_e2[bh * 1024 + n];
    __syncthreads();

    const int i0w = hv * 512 + w * 32;
    const int gid = lane >> 2, tig = lane & 3;     // mma thread coords
    const int lr = lane >> 3, lj = lane & 7;       // phase-A coords
    const int jb = lj << 2;
    float* phi = sm + SM_P + w * PW;
    float* plo = phi + 32 * ROWF;
    const float maxe2 = g_maxe2[bh];

    float e1v[8], mneg[8], sums[8];
#pragma unroll
    for (int p = 0; p < 8; p++) {
        float e = g_e1[bh * 1024 + i0w + p * 4 + lr];
        e1v[p] = e;
        float s = e + maxe2;
        s = fmaxf(s, 0.2f * s);          // leaky upper bound on all scores of the row
        mneg[p] = -s * LOG2E;
        sums[p] = 0.0f;
    }

    float c[2][4][4];
#pragma unroll
    for (int mt = 0; mt < 2; mt++)
#pragma unroll
        for (int nt = 0; nt < 4; nt++)
#pragma unroll
            for (int q = 0; q < 4; q++) c[mt][nt][q] = 0.0f;

    const int* adjb = adj + (size_t)(b * 1024 + i0w) * 1024;
    const float* Bhi = g_Bhi + (size_t)bh * 32768;
    const float* Blo = g_Blo + (size_t)bh * 32768;

    // B-fragment prefetch (chunk 0): lane (gid,tig) -> [d0+gid]*8 + tig*2
    uint2 bhn[4], bln[4];
#pragma unroll
    for (int nt = 0; nt < 4; nt++) {
        int o = (nt * 8 + gid) * 8 + tig * 2;
        bhn[nt] = *(const uint2*)&Bhi[o];
        bln[nt] = *(const uint2*)&Blo[o];
    }

    for (int jt = 0; jt < 32; jt++) {
        const int J0 = jt * 32;
        // ---- phase A: 32 rows x 32 j; 8 lanes cover one row, 4 rows per pass ----
        float4 ej4 = *(const float4*)&e2s[J0 + jb];
        float ej[4] = {ej4.x, ej4.y, ej4.z, ej4.w};
#pragma unroll
        for (int half = 0; half < 2; half++) {
            int4 ab[4];
#pragma unroll
            for (int q = 0; q < 4; q++) {
                int r = (half * 4 + q) * 4 + lr;
                ab[q] = *(const int4*)&adjb[(size_t)r * 1024 + J0 + jb];
            }
#pragma unroll
            for (int q = 0; q < 4; q++) {
                int p = half * 4 + q;
                int r = p * 4 + lr;
                int am[4] = {ab[q].x, ab[q].y, ab[q].z, ab[q].w};
                float fh[4], fl[4];
#pragma unroll
                for (int m = 0; m < 4; m++) {
                    float s = e1v[p] + ej[m];
                    s = fmaxf(s, 0.2f * s);
                    float arg = am[m] ? fmaf(s, LOG2E, mneg[p]) : -10000.0f;
                    float pe = ex2(arg);
                    sums[p] += pe;
                    float hh = tf32_hi(pe);
                    fh[m] = hh;
                    fl[m] = pe - hh;
                }
                *(float4*)&phi[r * ROWF + jb] = make_float4(fh[0], fh[1], fh[2], fh[3]);
                *(float4*)&plo[r * ROWF + jb] = make_float4(fl[0], fl[1], fl[2], fl[3]);
            }
        }
        __syncwarp();

        // ---- phase B: 4 chunks of 8 j; 3-split tf32 mma ----
#pragma unroll
        for (int cc = 0; cc < 4; cc++) {
            const int cj = cc * 8 + tig;
#pragma unroll
            for (int mt = 0; mt < 2; mt++) {
                const int ra = mt * 16 + gid, rb = ra + 8;
                uint32_t ah0 = __float_as_uint(phi[ra * ROWF + cj]);
                uint32_t ah1 = __float_as_uint(phi[rb * ROWF + cj]);
                uint32_t ah2 = __float_as_uint(phi[ra * ROWF + cj + 4]);
                uint32_t ah3 = __float_as_uint(phi[rb * ROWF + cj + 4]);
                uint32_t al0 = __float_as_uint(plo[ra * ROWF + cj]);
                uint32_t al1 = __float_as_uint(plo[rb * ROWF + cj]);
                uint32_t al2 = __float_as_uint(plo[ra * ROWF + cj + 4]);
                uint32_t al3 = __float_as_uint(plo[rb * ROWF + cj + 4]);
#pragma unroll
                for (int nt = 0; nt < 4; nt++) {
                    mma8(c[mt][nt], ah0, ah1, ah2, ah3, bhn[nt].x, bhn[nt].y);
                    mma8(c[mt][nt], al0, al1, al2, al3, bhn[nt].x, bhn[nt].y);
                    mma8(c[mt][nt], ah0, ah1, ah2, ah3, bln[nt].x, bln[nt].y);
                }
            }
            // prefetch B frags for next chunk (consumed next iter / next tile)
            const int gch = jt * 4 + cc + 1;
            if (gch < 128) {
                const float* ph = Bhi + gch * 256;
                const float* pl = Blo + gch * 256;
#pragma unroll
                for (int nt = 0; nt < 4; nt++) {
                    int o = (nt * 8 + gid) * 8 + tig * 2;
                    bhn[nt] = *(const uint2*)&ph[o];
                    bln[nt] = *(const uint2*)&pl[o];
                }
            }
        }
        __syncwarp();
    }

    // ---- row sums: reduce over the 8 j-lanes ----
#pragma unroll
    for (int p = 0; p < 8; p++) {
        float s = sums[p];
        s += __shfl_xor_sync(0xffffffffu, s, 1);
        s += __shfl_xor_sync(0xffffffffu, s, 2);
        s += __shfl_xor_sync(0xffffffffu, s, 4);
        if (lj == 0) sums_s[w * 32 + p * 4 + lr] = s;
    }
    __syncwarp();

    // ---- epilogue: normalize, +bias, relu, store ----
#pragma unroll
    for (int mt = 0; mt < 2; mt++) {
        const int ra = mt * 16 + gid, rb = ra + 8;
        const float inva = 1.0f / sums_s[w * 32 + ra];
        const float invb = 1.0f / sums_s[w * 32 + rb];
#pragma unroll
        for (int nt = 0; nt < 4; nt++) {
            int col = nt * 8 + tig * 2;
            float2 bv = *(const float2*)&bias[h * 32 + col];
            float2 oa, ob;
            oa.x = fmaxf(fmaf(c[mt][nt][0], inva, bv.x), 0.0f);
            oa.y = fmaxf(fmaf(c[mt][nt][1], inva, bv.y), 0.0f);
            ob.x = fmaxf(fmaf(c[mt][nt][2], invb, bv.x), 0.0f);
            ob.y = fmaxf(fmaf(c[mt][nt][3], invb, bv.y), 0.0f);
            *(float2*)&out[(size_t)((b << 10) + i0w + ra) * 256 + h * 32 + col] = oa;
            *(float2*)&out[(size_t)((b << 10) + i0w + rb) * 256 + h * 32 + col] = ob;
        }
    }
}

// ---------------- launch ----------------
extern "C" void kernel_launch(void* const* d_in, const int* in_sizes, int n_in,
                              void* d_out, int out_size) {
    const float* nf   = (const float*)d_in[0];
    const int*   adj  = (const int*)d_in[1];
    const float* Wm   = (const float*)d_in[2];
    const float* av   = (const float*)d_in[3];
    const float* bias = (const float*)d_in[4];
    float* out = (float*)d_out;

    gemm_wh_kernel<<<dim3(64, 4, 1), 256>>>(nf, Wm);
    compute_e_kernel<<<64, 256>>>(av);
    prep_b_kernel<<<64, 256>>>();
    cudaFuncSetAttribute(gat_attn_mma,
                         cudaFuncAttributeMaxDynamicSharedMemorySize, ATTN_SMEM);
    gat_attn_mma<<<128, 512, ATTN_SMEM>>>(adj, bias, out);
}